// round 1
// baseline (speedup 1.0000x reference)
#include <cuda_runtime.h>
#include <stdint.h>

#define THRESH 0.05f
#define NBINS  4096
#define CAP    65536
#define MAXR   (1 << 19)

__device__ float        g_bs[MAXR];
__device__ unsigned int g_hist[NBINS];
__device__ unsigned int g_count;
__device__ unsigned int g_cutoff;
__device__ unsigned int g_cand_val[CAP];
__device__ unsigned int g_cand_idx[CAP];

// ---------------------------------------------------------------------------
// Kernel 1: precompute box_scores = person_score * object_score, zero hist.
// ---------------------------------------------------------------------------
__global__ void k_init(const float* __restrict__ ps, const float* __restrict__ os, int R) {
    int i = blockIdx.x * blockDim.x + threadIdx.x;
    if (i < R)     g_bs[i]   = ps[i] * os[i];
    if (i < NBINS) g_hist[i] = 0;
    if (i == 0)    g_count   = 0;
}

// ---------------------------------------------------------------------------
// Kernel 2: histogram of scores > THRESH into 4096 linear bins on [0,1).
// bin(v) = floor(v * 4096) is monotone, so suffix counts give exact
// candidate-set sizes per cutoff.
// ---------------------------------------------------------------------------
__global__ void k_hist(const float4* __restrict__ hoi4, unsigned int nvec,
                       unsigned int N, unsigned int K) {
    __shared__ unsigned int sh[NBINS];
    for (int i = threadIdx.x; i < NBINS; i += blockDim.x) sh[i] = 0;
    __syncthreads();

    unsigned int stride = gridDim.x * blockDim.x;
    for (unsigned int q = blockIdx.x * blockDim.x + threadIdx.x; q < nvec; q += stride) {
        float4 h = hoi4[q];
        unsigned int e = q * 4u;
        unsigned int r = e / K;
        unsigned int c = e - r * K;
        float bs0 = g_bs[r];
        float bs1 = (c + 3 >= K) ? g_bs[r + 1] : bs0;
        float hv[4] = {h.x, h.y, h.z, h.w};
        #pragma unroll
        for (int j = 0; j < 4; j++) {
            float bs = (c + (unsigned)j < K) ? bs0 : bs1;
            float v  = hv[j] * bs;
            if (v > THRESH) {
                unsigned int b = (unsigned int)(v * (float)NBINS);
                if (b > NBINS - 1) b = NBINS - 1;
                atomicAdd(&sh[b], 1u);
            }
        }
    }
    // tail (N not multiple of 4)
    if (blockIdx.x == 0 && threadIdx.x == 0) {
        for (unsigned int e = nvec * 4u; e < N; e++) {
            unsigned int r = e / K;
            float v = ((const float*)hoi4)[e] * g_bs[r];
            if (v > THRESH) {
                unsigned int b = (unsigned int)(v * (float)NBINS);
                if (b > NBINS - 1) b = NBINS - 1;
                atomicAdd(&sh[b], 1u);
            }
        }
    }
    __syncthreads();
    for (int i = threadIdx.x; i < NBINS; i += blockDim.x)
        if (sh[i]) atomicAdd(&g_hist[i], sh[i]);
}

// ---------------------------------------------------------------------------
// Kernel 3: find smallest bin b such that suffix count >= topk.
// ---------------------------------------------------------------------------
__global__ void k_cutoff(int topk) {
    if (threadIdx.x == 0) {
        unsigned int cum = 0;
        int cut = 0;
        for (int b = NBINS - 1; b >= 0; b--) {
            cum += g_hist[b];
            if (cum >= (unsigned int)topk) { cut = b; break; }
        }
        g_cutoff = (unsigned int)cut;
    }
}

// ---------------------------------------------------------------------------
// Kernel 4: collect all candidates with bin(v) >= cutoff (and v > THRESH).
// ---------------------------------------------------------------------------
__global__ void k_collect(const float4* __restrict__ hoi4, unsigned int nvec,
                          unsigned int N, unsigned int K) {
    unsigned int cut = g_cutoff;
    unsigned int stride = gridDim.x * blockDim.x;
    for (unsigned int q = blockIdx.x * blockDim.x + threadIdx.x; q < nvec; q += stride) {
        float4 h = hoi4[q];
        unsigned int e = q * 4u;
        unsigned int r = e / K;
        unsigned int c = e - r * K;
        float bs0 = g_bs[r];
        float bs1 = (c + 3 >= K) ? g_bs[r + 1] : bs0;
        float hv[4] = {h.x, h.y, h.z, h.w};
        #pragma unroll
        for (int j = 0; j < 4; j++) {
            float bs = (c + (unsigned)j < K) ? bs0 : bs1;
            float v  = hv[j] * bs;
            if (v > THRESH) {
                unsigned int b = (unsigned int)(v * (float)NBINS);
                if (b > NBINS - 1) b = NBINS - 1;
                if (b >= cut) {
                    unsigned int pos = atomicAdd(&g_count, 1u);
                    if (pos < CAP) {
                        g_cand_val[pos] = __float_as_uint(v);
                        g_cand_idx[pos] = e + (unsigned)j;
                    }
                }
            }
        }
    }
    if (blockIdx.x == 0 && threadIdx.x == 0) {
        for (unsigned int e = nvec * 4u; e < N; e++) {
            unsigned int r = e / K;
            float v = ((const float*)hoi4)[e] * g_bs[r];
            if (v > THRESH) {
                unsigned int b = (unsigned int)(v * (float)NBINS);
                if (b > NBINS - 1) b = NBINS - 1;
                if (b >= cut) {
                    unsigned int pos = atomicAdd(&g_count, 1u);
                    if (pos < CAP) {
                        g_cand_val[pos] = __float_as_uint(v);
                        g_cand_idx[pos] = e;
                    }
                }
            }
        }
    }
}

// ---------------------------------------------------------------------------
// Kernel 5: exact rank (value desc, index asc — matches jax top_k ties),
// then gather everything into the flattened output:
//   [0,T)      scores
//   [T,5T)     person_boxes (T,4)
//   [5T,9T)    object_boxes (T,4)
//   [9T,10T)   object_classes
//   [10T,11T)  action_classes
//   [11T,12T)  valid
// ---------------------------------------------------------------------------
__global__ void k_final(const float4* __restrict__ pb, const float4* __restrict__ ob,
                        const int* __restrict__ ocls, float* __restrict__ out,
                        unsigned int K, int T) {
    unsigned int n = g_count;
    if (n > CAP) n = CAP;
    int tid = threadIdx.x;

    for (unsigned int i = tid; i < n; i += blockDim.x) {
        unsigned int vb = g_cand_val[i];
        unsigned int ix = g_cand_idx[i];
        unsigned int rank = 0;
        for (unsigned int j = 0; j < n; j++) {
            unsigned int vj = g_cand_val[j];
            if (vj > vb || (vj == vb && g_cand_idx[j] < ix)) rank++;
        }
        if (rank < (unsigned int)T) {
            float v = __uint_as_float(vb);
            unsigned int pair = ix / K;
            unsigned int act  = ix - pair * K;
            out[rank] = v;
            float4 p = pb[pair];
            float4 o = ob[pair];
            out[T  + 4 * rank + 0] = p.x;
            out[T  + 4 * rank + 1] = p.y;
            out[T  + 4 * rank + 2] = p.z;
            out[T  + 4 * rank + 3] = p.w;
            out[5 * T + 4 * rank + 0] = o.x;
            out[5 * T + 4 * rank + 1] = o.y;
            out[5 * T + 4 * rank + 2] = o.z;
            out[5 * T + 4 * rank + 3] = o.w;
            out[9 * T + rank]  = (float)ocls[pair];
            out[10 * T + rank] = (float)act;
            out[11 * T + rank] = 1.0f;
        }
    }

    // Pad unfilled slots (only when fewer than T candidates exist — not
    // expected for this data distribution).
    for (int s = tid; s < T; s += blockDim.x) {
        if ((unsigned int)s >= n) {
            out[s] = 0.0f;
            #pragma unroll
            for (int d = 0; d < 4; d++) {
                out[T + 4 * s + d]     = 0.0f;
                out[5 * T + 4 * s + d] = 0.0f;
            }
            out[9 * T + s]  = 0.0f;
            out[10 * T + s] = 0.0f;
            out[11 * T + s] = 0.0f;
        }
    }
}

// ---------------------------------------------------------------------------
extern "C" void kernel_launch(void* const* d_in, const int* in_sizes, int n_in,
                              void* d_out, int out_size) {
    const float* pb   = (const float*)d_in[0];
    const float* ob   = (const float*)d_in[1];
    const float* ps   = (const float*)d_in[2];
    const float* os   = (const float*)d_in[3];
    const int*   ocls = (const int*)d_in[4];
    const float* hoi  = (const float*)d_in[5];

    int R = in_sizes[2];
    unsigned int N = (unsigned int)in_sizes[5];
    unsigned int K = N / (unsigned int)R;
    int T = out_size / 12;
    unsigned int nvec = N / 4u;

    int initN = (R > NBINS ? R : NBINS);
    k_init<<<(initN + 255) / 256, 256>>>(ps, os, R);

    int blocks = 1184;  // 148 SMs * 8
    k_hist<<<blocks, 256>>>((const float4*)hoi, nvec, N, K);
    k_cutoff<<<1, 32>>>(T);
    k_collect<<<blocks, 256>>>((const float4*)hoi, nvec, N, K);
    k_final<<<1, 1024>>>((const float4*)pb, (const float4*)ob, ocls, (float*)d_out, K, T);
}

// round 2
// speedup vs baseline: 1.0551x; 1.0551x over previous
#include <cuda_runtime.h>
#include <stdint.h>

#define THRESH   0.05f
#define SPEC     0.95f      // speculative collection cutoff (fast path)
#define NBINS    4096
#define CAP      65536
#define RANKMAX  4096
#define MAXR     (1 << 19)

__device__ float        g_bs[MAXR];
__device__ unsigned int g_hist[NBINS];
__device__ unsigned int g_count;      // fast-path candidate count
__device__ unsigned int g_count2;     // fallback candidate count
__device__ unsigned int g_mode;       // 0 = fast path ok, 1 = need fallback
__device__ unsigned int g_cutoff;
__device__ unsigned int g_cand_val[CAP];
__device__ unsigned int g_cand_idx[CAP];
__device__ unsigned int g_cand2_val[CAP];
__device__ unsigned int g_cand2_idx[CAP];

// ---------------------------------------------------------------------------
// Kernel 1: box_scores = ps*os; zero hist + counters.
// ---------------------------------------------------------------------------
__global__ void k_init(const float* __restrict__ ps, const float* __restrict__ os, int R) {
    int i = blockIdx.x * blockDim.x + threadIdx.x;
    if (i < R)     g_bs[i]   = ps[i] * os[i];
    if (i < NBINS) g_hist[i] = 0;
    if (i == 0) { g_count = 0; g_count2 = 0; g_mode = 0; }
}

// ---------------------------------------------------------------------------
// Kernel 2 (THE pass): stream hoi once, collect v > SPEC candidates.
// Magic-multiply division replaces e/K. Unroll x4 for MLP.
// ---------------------------------------------------------------------------
__device__ __forceinline__ void spec_push(float v, unsigned int e) {
    if (v > SPEC) {
        unsigned int pos = atomicAdd(&g_count, 1u);
        if (pos < CAP) {
            g_cand_val[pos] = __float_as_uint(v);
            g_cand_idx[pos] = e;
        }
    }
}

__device__ __forceinline__ void proc4(const float4& h, unsigned int e,
                                      unsigned int K, unsigned long long magic) {
    unsigned int r = (unsigned int)(((unsigned long long)e * magic) >> 33);
    unsigned int c = e - r * K;
    float bs0 = g_bs[r];
    float v0, v1, v2, v3;
    if (c + 3 < K) {
        v0 = h.x * bs0; v1 = h.y * bs0; v2 = h.z * bs0; v3 = h.w * bs0;
    } else {
        float bs1 = g_bs[r + 1];
        v0 = h.x * bs0;
        v1 = h.y * ((c + 1 < K) ? bs0 : bs1);
        v2 = h.z * ((c + 2 < K) ? bs0 : bs1);
        v3 = h.w * ((c + 3 < K) ? bs0 : bs1);
    }
    spec_push(v0, e); spec_push(v1, e + 1); spec_push(v2, e + 2); spec_push(v3, e + 3);
}

__global__ void k_pass1(const float4* __restrict__ hoi4, unsigned int nvec,
                        unsigned int N, unsigned int K, unsigned long long magic) {
    unsigned int stride = gridDim.x * blockDim.x;
    unsigned int q = blockIdx.x * blockDim.x + threadIdx.x;
    // 4-way unrolled grid-stride: 4 independent 16B loads in flight per thread
    for (; q + 3u * stride < nvec; q += 4u * stride) {
        float4 h0 = hoi4[q];
        float4 h1 = hoi4[q + stride];
        float4 h2 = hoi4[q + 2u * stride];
        float4 h3 = hoi4[q + 3u * stride];
        proc4(h0, q * 4u, K, magic);
        proc4(h1, (q + stride) * 4u, K, magic);
        proc4(h2, (q + 2u * stride) * 4u, K, magic);
        proc4(h3, (q + 3u * stride) * 4u, K, magic);
    }
    for (; q < nvec; q += stride) {
        float4 h = hoi4[q];
        proc4(h, q * 4u, K, magic);
    }
    // scalar tail (N not multiple of 4)
    if (blockIdx.x == 0 && threadIdx.x == 0) {
        for (unsigned int e = nvec * 4u; e < N; e++) {
            unsigned int r = (unsigned int)(((unsigned long long)e * magic) >> 33);
            float v = ((const float*)hoi4)[e] * g_bs[r];
            spec_push(v, e);
        }
    }
}

// ---------------------------------------------------------------------------
// Kernel 3: decide fast vs fallback.
// Fast path valid iff: count >= topk (top-k fully contained in candidates,
// since ALL values > SPEC were collected) and count small enough to rank.
// ---------------------------------------------------------------------------
__global__ void k_check(int topk) {
    if (threadIdx.x == 0) {
        unsigned int n = g_count;
        g_mode = (n >= (unsigned int)topk && n <= RANKMAX) ? 0u : 1u;
    }
}

// ---------------------------------------------------------------------------
// Fallback kernels (early-exit when fast path succeeded).
// ---------------------------------------------------------------------------
__global__ void k_hist_fb(const float4* __restrict__ hoi4, unsigned int nvec,
                          unsigned int N, unsigned int K, unsigned long long magic) {
    if (g_mode == 0u) return;
    __shared__ unsigned int sh[NBINS];
    for (int i = threadIdx.x; i < NBINS; i += blockDim.x) sh[i] = 0;
    __syncthreads();
    unsigned int stride = gridDim.x * blockDim.x;
    for (unsigned int q = blockIdx.x * blockDim.x + threadIdx.x; q < nvec; q += stride) {
        float4 h = hoi4[q];
        unsigned int e = q * 4u;
        unsigned int r = (unsigned int)(((unsigned long long)e * magic) >> 33);
        unsigned int c = e - r * K;
        float bs0 = g_bs[r];
        float bs1 = (c + 3 >= K) ? g_bs[r + 1] : bs0;
        float hv[4] = {h.x, h.y, h.z, h.w};
        #pragma unroll
        for (int j = 0; j < 4; j++) {
            float bs = (c + (unsigned)j < K) ? bs0 : bs1;
            float v  = hv[j] * bs;
            if (v > THRESH) {
                unsigned int b = (unsigned int)(v * (float)NBINS);
                if (b > NBINS - 1) b = NBINS - 1;
                atomicAdd(&sh[b], 1u);
            }
        }
    }
    if (blockIdx.x == 0 && threadIdx.x == 0) {
        for (unsigned int e = nvec * 4u; e < N; e++) {
            unsigned int r = (unsigned int)(((unsigned long long)e * magic) >> 33);
            float v = ((const float*)hoi4)[e] * g_bs[r];
            if (v > THRESH) {
                unsigned int b = (unsigned int)(v * (float)NBINS);
                if (b > NBINS - 1) b = NBINS - 1;
                atomicAdd(&sh[b], 1u);
            }
        }
    }
    __syncthreads();
    for (int i = threadIdx.x; i < NBINS; i += blockDim.x)
        if (sh[i]) atomicAdd(&g_hist[i], sh[i]);
}

__global__ void k_cutoff_fb(int topk) {
    if (g_mode == 0u) return;
    if (threadIdx.x == 0) {
        unsigned int cum = 0;
        int cut = 0;
        for (int b = NBINS - 1; b >= 0; b--) {
            cum += g_hist[b];
            if (cum >= (unsigned int)topk) { cut = b; break; }
        }
        g_cutoff = (unsigned int)cut;
    }
}

__global__ void k_collect_fb(const float4* __restrict__ hoi4, unsigned int nvec,
                             unsigned int N, unsigned int K, unsigned long long magic) {
    if (g_mode == 0u) return;
    unsigned int cut = g_cutoff;
    unsigned int stride = gridDim.x * blockDim.x;
    for (unsigned int q = blockIdx.x * blockDim.x + threadIdx.x; q < nvec; q += stride) {
        float4 h = hoi4[q];
        unsigned int e = q * 4u;
        unsigned int r = (unsigned int)(((unsigned long long)e * magic) >> 33);
        unsigned int c = e - r * K;
        float bs0 = g_bs[r];
        float bs1 = (c + 3 >= K) ? g_bs[r + 1] : bs0;
        float hv[4] = {h.x, h.y, h.z, h.w};
        #pragma unroll
        for (int j = 0; j < 4; j++) {
            float bs = (c + (unsigned)j < K) ? bs0 : bs1;
            float v  = hv[j] * bs;
            if (v > THRESH) {
                unsigned int b = (unsigned int)(v * (float)NBINS);
                if (b > NBINS - 1) b = NBINS - 1;
                if (b >= cut) {
                    unsigned int pos = atomicAdd(&g_count2, 1u);
                    if (pos < CAP) {
                        g_cand2_val[pos] = __float_as_uint(v);
                        g_cand2_idx[pos] = e + (unsigned)j;
                    }
                }
            }
        }
    }
    if (blockIdx.x == 0 && threadIdx.x == 0) {
        for (unsigned int e = nvec * 4u; e < N; e++) {
            unsigned int r = (unsigned int)(((unsigned long long)e * magic) >> 33);
            float v = ((const float*)hoi4)[e] * g_bs[r];
            if (v > THRESH) {
                unsigned int b = (unsigned int)(v * (float)NBINS);
                if (b > NBINS - 1) b = NBINS - 1;
                if (b >= cut) {
                    unsigned int pos = atomicAdd(&g_count2, 1u);
                    if (pos < CAP) {
                        g_cand2_val[pos] = __float_as_uint(v);
                        g_cand2_idx[pos] = e;
                    }
                }
            }
        }
    }
}

// ---------------------------------------------------------------------------
// Final: exact rank (val desc, idx asc) of <= RANKMAX candidates in shared,
// then gather into flat output:
//   [0,T) scores | [T,5T) pboxes | [5T,9T) oboxes | [9T,10T) ocls
//   [10T,11T) action | [11T,12T) valid
// ---------------------------------------------------------------------------
__global__ void k_final(const float4* __restrict__ pb, const float4* __restrict__ ob,
                        const int* __restrict__ ocls, float* __restrict__ out,
                        unsigned int K, int T, unsigned long long magic) {
    __shared__ unsigned int sval[RANKMAX];
    __shared__ unsigned int sidx[RANKMAX];
    int tid = threadIdx.x;
    unsigned int mode = g_mode;
    unsigned int n;
    if (mode == 0u) {
        n = g_count; if (n > RANKMAX) n = RANKMAX;
        for (unsigned int i = tid; i < n; i += blockDim.x) {
            sval[i] = g_cand_val[i];
            sidx[i] = g_cand_idx[i];
        }
    } else {
        n = g_count2; if (n > RANKMAX) n = RANKMAX;
        for (unsigned int i = tid; i < n; i += blockDim.x) {
            sval[i] = g_cand2_val[i];
            sidx[i] = g_cand2_idx[i];
        }
    }
    __syncthreads();

    for (unsigned int i = tid; i < n; i += blockDim.x) {
        unsigned int vb = sval[i];
        unsigned int ix = sidx[i];
        unsigned int rank = 0;
        for (unsigned int j = 0; j < n; j++) {
            unsigned int vj = sval[j];
            if (vj > vb || (vj == vb && sidx[j] < ix)) rank++;
        }
        if (rank < (unsigned int)T) {
            float v = __uint_as_float(vb);
            unsigned int pair = (unsigned int)(((unsigned long long)ix * magic) >> 33);
            unsigned int act  = ix - pair * K;
            out[rank] = v;
            float4 p = pb[pair];
            float4 o = ob[pair];
            out[T + 4 * rank + 0] = p.x;
            out[T + 4 * rank + 1] = p.y;
            out[T + 4 * rank + 2] = p.z;
            out[T + 4 * rank + 3] = p.w;
            out[5 * T + 4 * rank + 0] = o.x;
            out[5 * T + 4 * rank + 1] = o.y;
            out[5 * T + 4 * rank + 2] = o.z;
            out[5 * T + 4 * rank + 3] = o.w;
            out[9 * T + rank]  = (float)ocls[pair];
            out[10 * T + rank] = (float)act;
            out[11 * T + rank] = 1.0f;
        }
    }

    // pad unfilled slots if fewer than T candidates
    for (int s = tid; s < T; s += blockDim.x) {
        if ((unsigned int)s >= n) {
            out[s] = 0.0f;
            #pragma unroll
            for (int d = 0; d < 4; d++) {
                out[T + 4 * s + d]     = 0.0f;
                out[5 * T + 4 * s + d] = 0.0f;
            }
            out[9 * T + s]  = 0.0f;
            out[10 * T + s] = 0.0f;
            out[11 * T + s] = 0.0f;
        }
    }
}

// ---------------------------------------------------------------------------
extern "C" void kernel_launch(void* const* d_in, const int* in_sizes, int n_in,
                              void* d_out, int out_size) {
    const float* pb   = (const float*)d_in[0];
    const float* ob   = (const float*)d_in[1];
    const float* ps   = (const float*)d_in[2];
    const float* os   = (const float*)d_in[3];
    const int*   ocls = (const int*)d_in[4];
    const float* hoi  = (const float*)d_in[5];

    int R = in_sizes[2];
    unsigned int N = (unsigned int)in_sizes[5];
    unsigned int K = N / (unsigned int)R;
    int T = out_size / 12;
    unsigned int nvec = N / 4u;
    // magic for exact floor(e/K), e < 2^33/K
    unsigned long long magic = ((1ULL << 33) + K - 1) / K;

    int initN = (R > NBINS ? R : NBINS);
    k_init<<<(initN + 255) / 256, 256>>>(ps, os, R);

    int blocks = 1184;  // 148 SMs * 8
    k_pass1<<<blocks, 256>>>((const float4*)hoi, nvec, N, K, magic);
    k_check<<<1, 32>>>(T);
    k_hist_fb<<<blocks, 256>>>((const float4*)hoi, nvec, N, K, magic);
    k_cutoff_fb<<<1, 32>>>(T);
    k_collect_fb<<<blocks, 256>>>((const float4*)hoi, nvec, N, K, magic);
    k_final<<<1, 1024>>>((const float4*)pb, (const float4*)ob, ocls, (float*)d_out,
                         K, T, magic);
}